// round 14
// baseline (speedup 1.0000x reference)
#include <cuda_runtime.h>
#include <cuda_bf16.h>
#include <cstdint>

// Problem constants (fixed shapes per reference)
#define B_ROWS   4096
#define N_COLS   64
#define BIN      256
#define TOT      (N_COLS * BIN)   // 16384

// Persistent grid: 3 CTAs/SM on 148 SMs (smem-limited).
#define GRID     444

// Per-warp cp.async pipeline: 4 stages, each = 1 column (256 L + 256 G floats).
#define NST           4
#define STAGE_FLOATS  512
#define DYN_SMEM      (8 * NST * STAGE_FLOATS * 4)   // 65536 bytes

// Scratch: per-block partials + last-block ticket counter (no allocs allowed).
__device__ float g_block_partials[GRID];
__device__ unsigned int g_ticket = 0;   // reset to 0 by the last block each launch

static __device__ __forceinline__ uint32_t smem_u32(const void* p) {
    return (uint32_t)__cvta_generic_to_shared(p);
}

static __device__ __forceinline__ void cp16(uint32_t dst, const float* src) {
    asm volatile("cp.async.cg.shared.global [%0], [%1], 16;"
                 :: "r"(dst), "l"(src) : "memory");
}

// Persistent kernel with PER-WARP async pipelines (no block-level sync in the
// hot loop). Each warp owns 8 columns per row (cols wid*8..wid*8+7) and
// streams them through a private 4-stage smem ring via cp.async.cg; loads are
// fire-and-forget so the LSU stays busy through the exp/shfl phase. z[target]
// is read from smem (no extra global traffic). No max-subtraction: z bounded
// (logits ~N(0,1), gumbel <= ~23), fp32-safe.
__global__ __launch_bounds__(256, 3)
void obs_loss_kernel(const float* __restrict__ logits,
                     const float* __restrict__ gumbel,
                     const int* __restrict__ mask,      // jax bool -> int32
                     const int* __restrict__ targets,
                     float* __restrict__ out)
{
    extern __shared__ float dyn[];

    const int tid  = threadIdx.x;
    const int wid  = tid >> 5;
    const int lane = tid & 31;
    const int bid  = blockIdx.x;

    float* wbase = dyn + wid * (NST * STAGE_FLOATS);

    const int nrows = (B_ROWS - 1 - bid) / GRID + 1;
    const int total = nrows * 8;     // columns this warp processes

    // Issue stage k: copy column (row(k), col(k)) into ring slot k%NST.
    auto issue = [&](int k) {
        const int row = bid + (k >> 3) * GRID;
        const int col = wid * 8 + (k & 7);
        const float* Ls = logits + (size_t)row * TOT + col * BIN;
        const float* Gs = gumbel + (size_t)row * TOT + col * BIN;
        float* st = wbase + (k & (NST - 1)) * STAGE_FLOATS;
        const uint32_t dL = smem_u32(st);
        const uint32_t dG = smem_u32(st + 256);
        cp16(dL + lane * 16,       Ls + lane * 4);
        cp16(dL + 512 + lane * 16, Ls + 128 + lane * 4);
        cp16(dG + lane * 16,       Gs + lane * 4);
        cp16(dG + 512 + lane * 16, Gs + 128 + lane * 4);
        asm volatile("cp.async.commit_group;" ::: "memory");
    };

    // Prologue: 3 stages in flight (total >= 72 always, no guards needed).
    issue(0); issue(1); issue(2);

    float acc = 0.0f;

    for (int k = 0; k < total; ++k) {
        const int row = bid + (k >> 3) * GRID;
        const int col = wid * 8 + (k & 7);

        // Scattered scalars fetched before the data wait (latency overlaps).
        int t = 0, mk = 1;
        if (lane == 0) {
            t  = __ldg(&targets[row * N_COLS + col]);
            mk = __ldg(&mask[(size_t)row * TOT + col * BIN + t]);
        }

        // Wait for stage k (tail-correct laddering).
        const int rem = total - 1 - k;
        if (rem >= 2)      asm volatile("cp.async.wait_group 2;" ::: "memory");
        else if (rem == 1) asm volatile("cp.async.wait_group 1;" ::: "memory");
        else               asm volatile("cp.async.wait_group 0;" ::: "memory");
        __syncwarp();   // cross-lane visibility of the async copies

        const float* L = wbase + (k & (NST - 1)) * STAGE_FLOATS;
        const float* G = L + 256;

        float4 a0 = *reinterpret_cast<const float4*>(L + lane * 4);
        float4 a1 = *reinterpret_cast<const float4*>(L + 128 + lane * 4);
        float4 b0 = *reinterpret_cast<const float4*>(G + lane * 4);
        float4 b1 = *reinterpret_cast<const float4*>(G + 128 + lane * 4);

        float s = __expf(a0.x + b0.x) + __expf(a0.y + b0.y)
                + __expf(a0.z + b0.z) + __expf(a0.w + b0.w)
                + __expf(a1.x + b1.x) + __expf(a1.y + b1.y)
                + __expf(a1.z + b1.z) + __expf(a1.w + b1.w);

        #pragma unroll
        for (int off = 16; off > 0; off >>= 1)
            s += __shfl_xor_sync(0xFFFFFFFFu, s, off);

        if (lane == 0 && !mk) {
            const float zt = L[t] + G[t];
            acc += (__logf(s) - zt);     // -(z_t - lse)
        }

        __syncwarp();   // all lanes done reading before slot reuse
        if (k + 3 < total) issue(k + 3);
    }

    // One block reduce at the very end.
    #pragma unroll
    for (int off = 16; off > 0; off >>= 1)
        acc += __shfl_xor_sync(0xFFFFFFFFu, acc, off);

    __shared__ float sacc[8];
    __shared__ bool  s_last;
    if (lane == 0) sacc[wid] = acc;
    __syncthreads();

    if (tid == 0) {
        float s = 0.0f;
        #pragma unroll
        for (int i = 0; i < 8; ++i) s += sacc[i];
        g_block_partials[bid] = s;
        __threadfence();                                   // publish partial
        unsigned int tk = atomicAdd(&g_ticket, 1u);
        s_last = (tk == (unsigned int)(GRID - 1));
    }
    __syncthreads();

    // Last block performs the final deterministic reduction over 444 partials.
    if (s_last) {
        float s = 0.0f;
        for (int i = tid; i < GRID; i += 256)
            s += g_block_partials[i];
        #pragma unroll
        for (int off = 16; off > 0; off >>= 1)
            s += __shfl_xor_sync(0xFFFFFFFFu, s, off);
        if (lane == 0) sacc[wid] = s;
        __syncthreads();
        if (tid == 0) {
            float loss = 0.0f;
            #pragma unroll
            for (int i = 0; i < 8; ++i) loss += sacc[i];
            out[0] = loss;
            out[1] = loss / ((float)B_ROWS * 0.69314718055994530942f);
            g_ticket = 0;                                  // reset for next replay
        }
    }
}

extern "C" void kernel_launch(void* const* d_in, const int* in_sizes, int n_in,
                              void* d_out, int out_size)
{
    const float* logits  = (const float*)d_in[0];
    const float* gumbel  = (const float*)d_in[1];
    const int*   mask    = (const int*)d_in[2];
    const int*   targets = (const int*)d_in[3];
    // d_in[4] = bin_size scalar (256), fixed — unused.
    (void)in_sizes; (void)n_in; (void)out_size;

    // Opt in to 64KB dynamic smem (host-side attribute; idempotent, no alloc).
    static bool attr_set = false;
    if (!attr_set) {
        cudaFuncSetAttribute(obs_loss_kernel,
                             cudaFuncAttributeMaxDynamicSharedMemorySize, DYN_SMEM);
        attr_set = true;
    }

    obs_loss_kernel<<<GRID, 256, DYN_SMEM>>>(logits, gumbel, mask, targets, (float*)d_out);
}

// round 15
// speedup vs baseline: 1.2673x; 1.2673x over previous
#include <cuda_runtime.h>
#include <cuda_bf16.h>

// Problem constants (fixed shapes per reference)
#define B_ROWS   4096
#define N_COLS   64
#define BIN      256
#define TOT      (N_COLS * BIN)   // 16384

// Persistent grid: 3 CTAs/SM on 148 SMs (85-reg budget -> 16-deep batches).
#define GRID     444

// Work unit = half a row (32 columns). 2 units per row.
#define NUNITS   (B_ROWS * 2)     // 8192

// Scratch: per-block partials + last-block ticket counter (no allocs allowed).
__device__ float g_block_partials[GRID];
__device__ unsigned int g_ticket = 0;   // reset to 0 by the last block each launch

// Persistent kernel, lean body + max-depth batching + fine-grained static
// work distribution. Work unit = (row, half): 32 columns. Flattening to 8192
// units cuts the load-imbalance tail from 8.4% (row granularity) to ~3%.
// Warp = 4 columns per unit via 8-lane groups (grp = lane>>3 selects the
// column, sub = lane&7 covers bins sub*4 + k*32). ALL 16 LDG.128 of a unit
// issue as a single front batch (8KB/warp in flight); nothing from z is
// retained -- the target bin's z is re-loaded by the group leader.
// No max-subtraction: z bounded (logits ~N(0,1), gumbel <= ~23), fp32-safe.
__global__ __launch_bounds__(256, 3)
void obs_loss_kernel(const float* __restrict__ logits,
                     const float* __restrict__ gumbel,
                     const int* __restrict__ mask,      // jax bool -> int32
                     const int* __restrict__ targets,
                     float* __restrict__ out)
{
    const int wid  = threadIdx.x >> 5;
    const int lane = threadIdx.x & 31;
    const int grp  = lane >> 3;    // which of the warp's 4 columns
    const int sub  = lane & 7;     // position within the 8-lane group

    float acc = 0.0f;   // accumulated across all units this block handles

    for (int u = blockIdx.x; u < NUNITS; u += GRID) {
        const int row  = u >> 1;
        const int half = u & 1;

        const float* lrow = logits + (size_t)row * TOT;
        const float* grow = gumbel + (size_t)row * TOT;

        const int mycol = half * 32 + wid * 4 + grp;
        const int cbase = mycol * BIN;

        // Group leader fetches the scattered tail data early so the latency
        // overlaps the streaming loads below.
        int   t_idx = 0, mk = 1;
        float zt = 0.0f;
        if (sub == 0) {
            t_idx = __ldg(&targets[row * N_COLS + mycol]);
            mk    = __ldg(&mask[(size_t)row * TOT + cbase + t_idx]);
            zt    = __ldg(lrow + cbase + t_idx) + __ldg(grow + cbase + t_idx);
        }

        const float* lp = lrow + cbase + sub * 4;
        const float* gp = grow + cbase + sub * 4;

        // ---- Single 16-deep front batch: 8KB per warp in flight.
        float4 a0 = __ldcs(reinterpret_cast<const float4*>(lp + 0 * 32));
        float4 a1 = __ldcs(reinterpret_cast<const float4*>(lp + 1 * 32));
        float4 a2 = __ldcs(reinterpret_cast<const float4*>(lp + 2 * 32));
        float4 a3 = __ldcs(reinterpret_cast<const float4*>(lp + 3 * 32));
        float4 a4 = __ldcs(reinterpret_cast<const float4*>(lp + 4 * 32));
        float4 a5 = __ldcs(reinterpret_cast<const float4*>(lp + 5 * 32));
        float4 a6 = __ldcs(reinterpret_cast<const float4*>(lp + 6 * 32));
        float4 a7 = __ldcs(reinterpret_cast<const float4*>(lp + 7 * 32));
        float4 b0 = __ldcs(reinterpret_cast<const float4*>(gp + 0 * 32));
        float4 b1 = __ldcs(reinterpret_cast<const float4*>(gp + 1 * 32));
        float4 b2 = __ldcs(reinterpret_cast<const float4*>(gp + 2 * 32));
        float4 b3 = __ldcs(reinterpret_cast<const float4*>(gp + 3 * 32));
        float4 b4 = __ldcs(reinterpret_cast<const float4*>(gp + 4 * 32));
        float4 b5 = __ldcs(reinterpret_cast<const float4*>(gp + 5 * 32));
        float4 b6 = __ldcs(reinterpret_cast<const float4*>(gp + 6 * 32));
        float4 b7 = __ldcs(reinterpret_cast<const float4*>(gp + 7 * 32));

        float s;
        s  = __expf(a0.x + b0.x) + __expf(a0.y + b0.y)
           + __expf(a0.z + b0.z) + __expf(a0.w + b0.w);
        s += __expf(a1.x + b1.x) + __expf(a1.y + b1.y)
           + __expf(a1.z + b1.z) + __expf(a1.w + b1.w);
        s += __expf(a2.x + b2.x) + __expf(a2.y + b2.y)
           + __expf(a2.z + b2.z) + __expf(a2.w + b2.w);
        s += __expf(a3.x + b3.x) + __expf(a3.y + b3.y)
           + __expf(a3.z + b3.z) + __expf(a3.w + b3.w);
        s += __expf(a4.x + b4.x) + __expf(a4.y + b4.y)
           + __expf(a4.z + b4.z) + __expf(a4.w + b4.w);
        s += __expf(a5.x + b5.x) + __expf(a5.y + b5.y)
           + __expf(a5.z + b5.z) + __expf(a5.w + b5.w);
        s += __expf(a6.x + b6.x) + __expf(a6.y + b6.y)
           + __expf(a6.z + b6.z) + __expf(a6.w + b6.w);
        s += __expf(a7.x + b7.x) + __expf(a7.y + b7.y)
           + __expf(a7.z + b7.z) + __expf(a7.w + b7.w);

        // Reduce within the 8-lane group: 3 shuffle levels for 4 columns.
        #pragma unroll
        for (int off = 4; off > 0; off >>= 1)
            s += __shfl_xor_sync(0xFFFFFFFFu, s, off);

        if (sub == 0 && !mk)
            acc += (__logf(s) - zt);   // -(z_t - lse)
    }

    // One block reduce at the very end (not per unit).
    #pragma unroll
    for (int off = 16; off > 0; off >>= 1)
        acc += __shfl_xor_sync(0xFFFFFFFFu, acc, off);

    __shared__ float sacc[8];
    __shared__ bool  s_last;
    if (lane == 0) sacc[wid] = acc;
    __syncthreads();

    if (threadIdx.x == 0) {
        float s = 0.0f;
        #pragma unroll
        for (int i = 0; i < 8; ++i) s += sacc[i];
        g_block_partials[blockIdx.x] = s;
        __threadfence();                                   // publish partial
        unsigned int t = atomicAdd(&g_ticket, 1u);
        s_last = (t == (unsigned int)(GRID - 1));
    }
    __syncthreads();

    // Last block performs the final deterministic reduction over 444 partials.
    if (s_last) {
        float s = 0.0f;
        for (int i = threadIdx.x; i < GRID; i += 256)
            s += g_block_partials[i];
        #pragma unroll
        for (int off = 16; off > 0; off >>= 1)
            s += __shfl_xor_sync(0xFFFFFFFFu, s, off);
        if (lane == 0) sacc[wid] = s;
        __syncthreads();
        if (threadIdx.x == 0) {
            float loss = 0.0f;
            #pragma unroll
            for (int i = 0; i < 8; ++i) loss += sacc[i];
            out[0] = loss;
            out[1] = loss / ((float)B_ROWS * 0.69314718055994530942f);
            g_ticket = 0;                                  // reset for next replay
        }
    }
}

extern "C" void kernel_launch(void* const* d_in, const int* in_sizes, int n_in,
                              void* d_out, int out_size)
{
    const float* logits  = (const float*)d_in[0];
    const float* gumbel  = (const float*)d_in[1];
    const int*   mask    = (const int*)d_in[2];
    const int*   targets = (const int*)d_in[3];
    // d_in[4] = bin_size scalar (256), fixed — unused.
    (void)in_sizes; (void)n_in; (void)out_size;

    obs_loss_kernel<<<GRID, 256>>>(logits, gumbel, mask, targets, (float*)d_out);
}

// round 16
// speedup vs baseline: 1.3388x; 1.0564x over previous
#include <cuda_runtime.h>
#include <cuda_bf16.h>

// Problem constants (fixed shapes per reference)
#define B_ROWS   4096
#define N_COLS   64
#define BIN      256
#define TOT      (N_COLS * BIN)   // 16384

// Persistent grid: 3 CTAs/SM on 148 SMs (85-reg budget -> 16-deep batches).
#define GRID     444

// Work unit = half a row (32 columns). 2 units per row.
#define NUNITS   (B_ROWS * 2)     // 8192

// Scratch: per-block partials + last-block ticket counter (no allocs allowed).
__device__ float g_block_partials[GRID];
__device__ unsigned int g_ticket = 0;   // reset to 0 by the last block each launch

// Persistent kernel combining R13's straight-line double-batching with
// fine-grained (half-row) work distribution:
//  - unit = (row, half) covering 32 columns; 8192 units over 444 blocks
//    -> 3% load-imbalance tail (vs 8.4% at row granularity).
//  - units are consumed in straight-line PAIRS so ptxas can roll the second
//    unit's 16-deep LDG.128 batch into the first unit's exp/shfl phase
//    (the property that made R13 fast).
// Warp = 4 columns per unit via 8-lane groups (grp = lane>>3 selects the
// column, sub = lane&7 covers bins sub*4 + k*32); nothing from z is retained
// (the target bin's z is re-loaded by the group leader). No max-subtraction:
// z bounded (logits ~N(0,1), gumbel <= ~23), fp32-safe.
__global__ __launch_bounds__(256, 3)
void obs_loss_kernel(const float* __restrict__ logits,
                     const float* __restrict__ gumbel,
                     const int* __restrict__ mask,      // jax bool -> int32
                     const int* __restrict__ targets,
                     float* __restrict__ out)
{
    const int wid  = threadIdx.x >> 5;
    const int lane = threadIdx.x & 31;
    const int grp  = lane >> 3;    // which of the warp's 4 columns
    const int sub  = lane & 7;     // position within the 8-lane group

    float acc = 0.0f;   // accumulated across all units this block handles

    auto do_unit = [&](int u) __attribute__((always_inline)) {
        const int row  = u >> 1;
        const int half = u & 1;

        const float* lrow = logits + (size_t)row * TOT;
        const float* grow = gumbel + (size_t)row * TOT;

        const int mycol = half * 32 + wid * 4 + grp;
        const int cbase = mycol * BIN;

        // Group leader fetches the scattered tail data early so the latency
        // overlaps the streaming loads below.
        int   t_idx = 0, mk = 1;
        float zt = 0.0f;
        if (sub == 0) {
            t_idx = __ldg(&targets[row * N_COLS + mycol]);
            mk    = __ldg(&mask[(size_t)row * TOT + cbase + t_idx]);
            zt    = __ldg(lrow + cbase + t_idx) + __ldg(grow + cbase + t_idx);
        }

        const float* lp = lrow + cbase + sub * 4;
        const float* gp = grow + cbase + sub * 4;

        // ---- Single 16-deep front batch: 8KB per warp in flight.
        float4 a0 = __ldcs(reinterpret_cast<const float4*>(lp + 0 * 32));
        float4 a1 = __ldcs(reinterpret_cast<const float4*>(lp + 1 * 32));
        float4 a2 = __ldcs(reinterpret_cast<const float4*>(lp + 2 * 32));
        float4 a3 = __ldcs(reinterpret_cast<const float4*>(lp + 3 * 32));
        float4 a4 = __ldcs(reinterpret_cast<const float4*>(lp + 4 * 32));
        float4 a5 = __ldcs(reinterpret_cast<const float4*>(lp + 5 * 32));
        float4 a6 = __ldcs(reinterpret_cast<const float4*>(lp + 6 * 32));
        float4 a7 = __ldcs(reinterpret_cast<const float4*>(lp + 7 * 32));
        float4 b0 = __ldcs(reinterpret_cast<const float4*>(gp + 0 * 32));
        float4 b1 = __ldcs(reinterpret_cast<const float4*>(gp + 1 * 32));
        float4 b2 = __ldcs(reinterpret_cast<const float4*>(gp + 2 * 32));
        float4 b3 = __ldcs(reinterpret_cast<const float4*>(gp + 3 * 32));
        float4 b4 = __ldcs(reinterpret_cast<const float4*>(gp + 4 * 32));
        float4 b5 = __ldcs(reinterpret_cast<const float4*>(gp + 5 * 32));
        float4 b6 = __ldcs(reinterpret_cast<const float4*>(gp + 6 * 32));
        float4 b7 = __ldcs(reinterpret_cast<const float4*>(gp + 7 * 32));

        float s;
        s  = __expf(a0.x + b0.x) + __expf(a0.y + b0.y)
           + __expf(a0.z + b0.z) + __expf(a0.w + b0.w);
        s += __expf(a1.x + b1.x) + __expf(a1.y + b1.y)
           + __expf(a1.z + b1.z) + __expf(a1.w + b1.w);
        s += __expf(a2.x + b2.x) + __expf(a2.y + b2.y)
           + __expf(a2.z + b2.z) + __expf(a2.w + b2.w);
        s += __expf(a3.x + b3.x) + __expf(a3.y + b3.y)
           + __expf(a3.z + b3.z) + __expf(a3.w + b3.w);
        s += __expf(a4.x + b4.x) + __expf(a4.y + b4.y)
           + __expf(a4.z + b4.z) + __expf(a4.w + b4.w);
        s += __expf(a5.x + b5.x) + __expf(a5.y + b5.y)
           + __expf(a5.z + b5.z) + __expf(a5.w + b5.w);
        s += __expf(a6.x + b6.x) + __expf(a6.y + b6.y)
           + __expf(a6.z + b6.z) + __expf(a6.w + b6.w);
        s += __expf(a7.x + b7.x) + __expf(a7.y + b7.y)
           + __expf(a7.z + b7.z) + __expf(a7.w + b7.w);

        // Reduce within the 8-lane group: 3 shuffle levels for 4 columns.
        #pragma unroll
        for (int off = 4; off > 0; off >>= 1)
            s += __shfl_xor_sync(0xFFFFFFFFu, s, off);

        if (sub == 0 && !mk)
            acc += (__logf(s) - zt);   // -(z_t - lse)
    };

    // Straight-line pairs (rolling cross-batch LDG issue) + single tail.
    const int bid     = blockIdx.x;
    const int myCount = (NUNITS - 1 - bid) / GRID + 1;   // 18 or 19
    int k = 0;
    for (; k + 1 < myCount; k += 2) {
        do_unit(bid + k * GRID);
        do_unit(bid + (k + 1) * GRID);
    }
    if (k < myCount)
        do_unit(bid + k * GRID);

    // One block reduce at the very end (not per unit).
    #pragma unroll
    for (int off = 16; off > 0; off >>= 1)
        acc += __shfl_xor_sync(0xFFFFFFFFu, acc, off);

    __shared__ float sacc[8];
    __shared__ bool  s_last;
    if (lane == 0) sacc[wid] = acc;
    __syncthreads();

    if (threadIdx.x == 0) {
        float s = 0.0f;
        #pragma unroll
        for (int i = 0; i < 8; ++i) s += sacc[i];
        g_block_partials[blockIdx.x] = s;
        __threadfence();                                   // publish partial
        unsigned int t = atomicAdd(&g_ticket, 1u);
        s_last = (t == (unsigned int)(GRID - 1));
    }
    __syncthreads();

    // Last block performs the final deterministic reduction over 444 partials.
    if (s_last) {
        float s = 0.0f;
        for (int i = threadIdx.x; i < GRID; i += 256)
            s += g_block_partials[i];
        #pragma unroll
        for (int off = 16; off > 0; off >>= 1)
            s += __shfl_xor_sync(0xFFFFFFFFu, s, off);
        if (lane == 0) sacc[wid] = s;
        __syncthreads();
        if (threadIdx.x == 0) {
            float loss = 0.0f;
            #pragma unroll
            for (int i = 0; i < 8; ++i) loss += sacc[i];
            out[0] = loss;
            out[1] = loss / ((float)B_ROWS * 0.69314718055994530942f);
            g_ticket = 0;                                  // reset for next replay
        }
    }
}

extern "C" void kernel_launch(void* const* d_in, const int* in_sizes, int n_in,
                              void* d_out, int out_size)
{
    const float* logits  = (const float*)d_in[0];
    const float* gumbel  = (const float*)d_in[1];
    const int*   mask    = (const int*)d_in[2];
    const int*   targets = (const int*)d_in[3];
    // d_in[4] = bin_size scalar (256), fixed — unused.
    (void)in_sizes; (void)n_in; (void)out_size;

    obs_loss_kernel<<<GRID, 256>>>(logits, gumbel, mask, targets, (float*)d_out);
}